// round 4
// baseline (speedup 1.0000x reference)
#include <cuda_runtime.h>
#include <cuda_bf16.h>

// VisbilityMask: out[b, ch, r, c] = 1 - (tn_z(vertex r,c) >= 0)
//
// Reference reduces (scatter .set last-wins + nonnegative angle weights =>
// only the SIGN of one face normal's z matters per vertex):
//   r>=1, c>=1 : face f2 of cell (r-1,c-1): p1=(r,c-1) p0=(r-1,c) p2=(r,c)
//   r==0, c>=1 : face f1 of cell (0,c-1):   p1=(1,c-1) p0=(0,c-1) p2=(0,c)
//   c==0       : same face as c==1  =>  mask[r][0] == mask[r][1]
// e0 = P(p1)-P(p0), e2 = P(p1)-P(p2), tn_z = e0x*e2y - e0y*e2x (x,y only).
//
// 1 thread = 4 consecutive c. 4x LDG.128 + 2x LDG.32 all independent and
// front-batched (MLP 6, no shuffle chain), compute, 3x STG.128.

#define G     512
#define NV    (G * G)          // 262144
#define BATCH 4

// sign of cross((p1-p0),(p1-p2)).z with explicit rn mul/sub (no FMA
// contraction => bit-identical sign to XLA's mul,mul,sub sequence)
__device__ __forceinline__ float vis(float p1x, float p1y,
                                     float p0x, float p0y,
                                     float p2x, float p2y)
{
    const float e0x = p1x - p0x;
    const float e0y = p1y - p0y;
    const float e2x = p1x - p2x;
    const float e2y = p1y - p2y;
    const float tnz = __fsub_rn(__fmul_rn(e0x, e2y), __fmul_rn(e0y, e2x));
    return (tnz >= 0.0f) ? 0.0f : 1.0f;
}

__global__ __launch_bounds__(256, 8)
void visibility_mask_v4(const float* __restrict__ X, float* __restrict__ out)
{
    const int tid = blockIdx.x * blockDim.x + threadIdx.x;  // 0 .. BATCH*NV/4-1
    const int b  = tid >> 16;            // 65536 quads per batch
    const int q  = tid & 65535;
    const int r  = q >> 7;               // 128 quads per row (4 warps per row)
    const int cq = q & 127;              // quad index; c0 = 4*cq

    const float* xs = X + (size_t)b * 3 * NV;   // x-plane
    const float* ys = xs + NV;                   // y-plane

    const float* Ax = xs + (size_t)r * G;        // own row
    const float* Ay = ys + (size_t)r * G;
    const int rb = (r > 0) ? (r - 1) : 1;        // "other" row
    const float* Bx = xs + (size_t)rb * G;
    const float* By = ys + (size_t)rb * G;

    // Front batch: 4x LDG.128 + 2x LDG.32, all independent.
    const float4 ax = ((const float4*)Ax)[cq];
    const float4 ay = ((const float4*)Ay)[cq];
    const float4 bx = ((const float4*)Bx)[cq];
    const float4 by = ((const float4*)By)[cq];
    const int cm1 = (cq > 0) ? (4 * cq - 1) : 0;  // clamped; cq==0 value unused
    const float axm1 = __ldg(Ax + cm1);
    const float aym1 = __ldg(Ay + cm1);

    float o0, o1, o2, o3;
    if (r > 0) {   // warp-uniform (r constant within each warp)
        // p1 = A[c-1], p0 = B[c], p2 = A[c]
        o0 = vis(axm1, aym1, bx.x, by.x, ax.x, ay.x);
        o1 = vis(ax.x, ay.x, bx.y, by.y, ax.y, ay.y);
        o2 = vis(ax.y, ay.y, bx.z, by.z, ax.z, ay.z);
        o3 = vis(ax.z, ay.z, bx.w, by.w, ax.w, ay.w);
    } else {
        // p1 = B[c-1], p0 = A[c-1], p2 = A[c]   (B = row 1, A = row 0)
        const float bxm1 = __ldg(Bx + cm1);
        const float bym1 = __ldg(By + cm1);
        o0 = vis(bxm1, bym1, axm1, aym1, ax.x, ay.x);
        o1 = vis(bx.x, by.x, ax.x, ay.x, ax.y, ay.y);
        o2 = vis(bx.y, by.y, ax.y, ay.y, ax.z, ay.z);
        o3 = vis(bx.z, by.z, ax.z, ay.z, ax.w, ay.w);
    }
    if (cq == 0) o0 = o1;   // mask[r][0] == mask[r][1] (same face, sign-equal)

    const float4 o4 = make_float4(o0, o1, o2, o3);
    float* ob = out + (size_t)b * 3 * NV + (size_t)r * G;
    ((float4*)(ob))[cq]          = o4;
    ((float4*)(ob + NV))[cq]     = o4;
    ((float4*)(ob + 2 * NV))[cq] = o4;
}

extern "C" void kernel_launch(void* const* d_in, const int* in_sizes, int n_in,
                              void* d_out, int out_size)
{
    const float* X = (const float*)d_in[0];   // [BATCH, 3, NV] float32
    float* out = (float*)d_out;               // [BATCH, 3, G, G] float32

    const int total = BATCH * NV / 4;         // 262144 threads
    visibility_mask_v4<<<total / 256, 256>>>(X, out);
}

// round 5
// speedup vs baseline: 1.2251x; 1.2251x over previous
#include <cuda_runtime.h>
#include <cuda_bf16.h>

// VisbilityMask: out[b, ch, r, c] = 1 - (tn_z(vertex r,c) >= 0)
//
// Reference reduces (scatter .set last-wins + nonnegative angle weights =>
// only the SIGN of one face normal's z matters per vertex):
//   r>=1, c>=1 : face f2 of cell (r-1,c-1): p1=(r,c-1) p0=(r-1,c) p2=(r,c)
//   r==0, c>=1 : face f1 of cell (0,c-1):   p1=(1,c-1) p0=(0,c-1) p2=(0,c)
//   c==0       : same face as c==1  =>  mask[r][0] == mask[r][1]
// e0 = P(p1)-P(p0), e2 = P(p1)-P(p2), tn_z = e0x*e2y - e0y*e2x (x,y only).
//
// Warm-L2 optimized (the bench replays with X resident in L2): exactly
// 4x LDG.128 per thread; c-1 neighbors via __shfl_up (cheap on resident
// data); real neighbor loads only on lane 0 (1/32 threads). Direct
// computation, no staging arrays (low regs, short predication).

#define G     512
#define NV    (G * G)          // 262144
#define BATCH 4
#define FULL  0xFFFFFFFFu

// sign of cross((p1-p0),(p1-p2)).z with explicit rn mul/sub (no FMA
// contraction => bit-identical sign to XLA's mul,mul,sub sequence)
__device__ __forceinline__ float vis(float p1x, float p1y,
                                     float p0x, float p0y,
                                     float p2x, float p2y)
{
    const float e0x = p1x - p0x;
    const float e0y = p1y - p0y;
    const float e2x = p1x - p2x;
    const float e2y = p1y - p2y;
    const float tnz = __fsub_rn(__fmul_rn(e0x, e2y), __fmul_rn(e0y, e2x));
    return (tnz >= 0.0f) ? 0.0f : 1.0f;
}

__global__ __launch_bounds__(256, 8)
void visibility_mask_v5(const float* __restrict__ X, float* __restrict__ out)
{
    const int tid = blockIdx.x * blockDim.x + threadIdx.x;  // 0 .. BATCH*NV/4-1
    const int b  = tid >> 16;            // 65536 quads per batch
    const int q  = tid & 65535;
    const int r  = q >> 7;               // 128 quads per row (4 warps per row)
    const int cq = q & 127;              // quad index; c0 = 4*cq
    const int lane = threadIdx.x & 31;

    const float* xs = X + (size_t)b * 3 * NV;   // x-plane
    const float* ys = xs + NV;                   // y-plane

    const float* Ax = xs + (size_t)r * G;        // own row
    const float* Ay = ys + (size_t)r * G;
    const int rb = (r > 0) ? (r - 1) : 1;        // "other" row
    const float* Bx = xs + (size_t)rb * G;
    const float* By = ys + (size_t)rb * G;

    // Exactly 4 vector loads per thread.
    const float4 ax = ((const float4*)Ax)[cq];
    const float4 ay = ((const float4*)Ay)[cq];
    const float4 bx = ((const float4*)Bx)[cq];
    const float4 by = ((const float4*)By)[cq];

    // c0-1 own-row neighbors from the previous lane's .w (warm-cheap).
    float axm1 = __shfl_up_sync(FULL, ax.w, 1);
    float aym1 = __shfl_up_sync(FULL, ay.w, 1);
    if (lane == 0 && cq > 0) {           // warp boundary inside a row
        const int cm1 = 4 * cq - 1;
        axm1 = __ldg(Ax + cm1);
        aym1 = __ldg(Ay + cm1);
    }
    // (cq==0: neighbor values unused — o0 is overwritten by o1 below.)

    float o0, o1, o2, o3;
    if (r > 0) {   // warp-uniform (r constant within each warp)
        // p1 = A[c-1], p0 = B[c], p2 = A[c]
        o0 = vis(axm1, aym1, bx.x, by.x, ax.x, ay.x);
        o1 = vis(ax.x, ay.x, bx.y, by.y, ax.y, ay.y);
        o2 = vis(ax.y, ay.y, bx.z, by.z, ax.z, ay.z);
        o3 = vis(ax.z, ay.z, bx.w, by.w, ax.w, ay.w);
    } else {
        // p1 = B[c-1], p0 = A[c-1], p2 = A[c]   (B = row 1, A = row 0)
        float bxm1 = __shfl_up_sync(FULL, bx.w, 1);
        float bym1 = __shfl_up_sync(FULL, by.w, 1);
        if (lane == 0 && cq > 0) {
            const int cm1 = 4 * cq - 1;
            bxm1 = __ldg(Bx + cm1);
            bym1 = __ldg(By + cm1);
        }
        o0 = vis(bxm1, bym1, axm1, aym1, ax.x, ay.x);
        o1 = vis(bx.x, by.x, ax.x, ay.x, ax.y, ay.y);
        o2 = vis(bx.y, by.y, ax.y, ay.y, ax.z, ay.z);
        o3 = vis(bx.z, by.z, ax.z, ay.z, ax.w, ay.w);
    }
    if (cq == 0) o0 = o1;   // mask[r][0] == mask[r][1] (same face, sign-equal)

    const float4 o4 = make_float4(o0, o1, o2, o3);
    float* ob = out + (size_t)b * 3 * NV + (size_t)r * G;
    ((float4*)(ob))[cq]          = o4;
    ((float4*)(ob + NV))[cq]     = o4;
    ((float4*)(ob + 2 * NV))[cq] = o4;
}

extern "C" void kernel_launch(void* const* d_in, const int* in_sizes, int n_in,
                              void* d_out, int out_size)
{
    const float* X = (const float*)d_in[0];   // [BATCH, 3, NV] float32
    float* out = (float*)d_out;               // [BATCH, 3, G, G] float32

    const int total = BATCH * NV / 4;         // 262144 threads
    visibility_mask_v5<<<total / 256, 256>>>(X, out);
}